// round 1
// baseline (speedup 1.0000x reference)
#include <cuda_runtime.h>
#include <math.h>

#define S_LEN   2048
#define D_MODEL 1024
#define TRIPLE  (3 * D_MODEL)
#define H_NUM   16
#define HD      64
#define CHUNK   128
#define NCHUNK  (S_LEN / CHUNK)   // 16
#define EPSV    1e-6f

// ---------------- scratch (no allocations allowed) ----------------
__device__ float g_qkv[(size_t)S_LEN * TRIPLE];              // 24 MB: [phi(q) | phi(k) | v]
__device__ float g_state[(size_t)H_NUM * NCHUNK * HD * HD];  // 4 MB : per-(h,chunk) KV states (inclusive prefix after K3)
__device__ float g_ksum[H_NUM * NCHUNK * HD];                // k-sum states
__device__ float g_attn[(size_t)S_LEN * D_MODEL];            // 8 MB : attention output

__device__ __forceinline__ float phi_fn(float x) {
    // elu(x)+1 : x>0 -> x+1, else exp(x)
    return x > 0.f ? x + 1.f : expf(x);
}

// ---------------- K1/K5: classic 128x128x8 fp32 SGEMM ----------------
// C[M,N] = A[M,K] @ B[K,N]; feature map applied to columns < phi_cols.
// All dims here are multiples of 128 (M=2048, N in {3072,1024}, K=1024).
__global__ __launch_bounds__(256) void sgemm_kernel(
    const float* __restrict__ A, const float* __restrict__ B, float* __restrict__ C,
    int M, int N, int K, int phi_cols)
{
    __shared__ float As[8][128];
    __shared__ float Bs[8][128];
    const int tid = threadIdx.x;
    const int bm = blockIdx.y, bn = blockIdx.x;
    const int tx = tid & 15, ty = tid >> 4;

    const float* Ablk = A + (size_t)bm * 128 * K;
    const float* Bblk = B + (size_t)bn * 128;

    const int a_row = tid >> 1;          // 0..127
    const int a_seg = (tid & 1) * 4;     // 0 or 4
    const int b_kk  = tid >> 5;          // 0..7
    const int b_n   = (tid & 31) * 4;    // 0..124

    float acc[8][8];
#pragma unroll
    for (int i = 0; i < 8; i++)
#pragma unroll
        for (int j = 0; j < 8; j++) acc[i][j] = 0.f;

    for (int k0 = 0; k0 < K; k0 += 8) {
        float4 av = *reinterpret_cast<const float4*>(Ablk + (size_t)a_row * K + k0 + a_seg);
        float4 bv = *reinterpret_cast<const float4*>(Bblk + (size_t)(k0 + b_kk) * N + b_n);
        __syncthreads();
        As[a_seg + 0][a_row] = av.x;
        As[a_seg + 1][a_row] = av.y;
        As[a_seg + 2][a_row] = av.z;
        As[a_seg + 3][a_row] = av.w;
        *reinterpret_cast<float4*>(&Bs[b_kk][b_n]) = bv;
        __syncthreads();
#pragma unroll
        for (int kk = 0; kk < 8; kk++) {
            float ar[8], br[8];
            *reinterpret_cast<float4*>(&ar[0]) = *reinterpret_cast<const float4*>(&As[kk][ty * 8]);
            *reinterpret_cast<float4*>(&ar[4]) = *reinterpret_cast<const float4*>(&As[kk][ty * 8 + 4]);
            *reinterpret_cast<float4*>(&br[0]) = *reinterpret_cast<const float4*>(&Bs[kk][tx * 8]);
            *reinterpret_cast<float4*>(&br[4]) = *reinterpret_cast<const float4*>(&Bs[kk][tx * 8 + 4]);
#pragma unroll
            for (int i = 0; i < 8; i++)
#pragma unroll
                for (int j = 0; j < 8; j++)
                    acc[i][j] = fmaf(ar[i], br[j], acc[i][j]);
        }
    }

    const bool apply_phi = (bn * 128) < phi_cols;  // phi_cols is a multiple of 128
#pragma unroll
    for (int i = 0; i < 8; i++) {
        const int row = bm * 128 + ty * 8 + i;
        float* crow = C + (size_t)row * N + bn * 128 + tx * 8;
        float vals[8];
#pragma unroll
        for (int j = 0; j < 8; j++) vals[j] = apply_phi ? phi_fn(acc[i][j]) : acc[i][j];
        *reinterpret_cast<float4*>(crow)     = *reinterpret_cast<float4*>(&vals[0]);
        *reinterpret_cast<float4*>(crow + 4) = *reinterpret_cast<float4*>(&vals[4]);
    }
}

// ---------------- K2: per-(head, chunk) local KV state + k-sum ----------------
// state[i][j] = sum_{t in chunk} phi_k[t][i] * v[t][j]   (64x64)
// ksum[i]     = sum_{t in chunk} phi_k[t][i]
__global__ __launch_bounds__(256) void chunk_state_kernel()
{
    __shared__ float Ks[64][64];
    __shared__ float Vs[64][64];
    const int c = blockIdx.x, h = blockIdx.y;
    const int tid = threadIdx.x;
    const int ti = (tid >> 4) * 4;   // 0..60
    const int tj = (tid & 15) * 4;   // 0..60

    float acc[4][4];
#pragma unroll
    for (int a = 0; a < 4; a++)
#pragma unroll
        for (int b = 0; b < 4; b++) acc[a][b] = 0.f;
    float ksum_acc = 0.f;

    for (int half = 0; half < 2; half++) {
        const int s0 = c * CHUNK + half * 64;
        const float* base = g_qkv + (size_t)s0 * TRIPLE + h * HD;
        for (int e = tid; e < 64 * HD; e += 256) {
            const int r = e >> 6, d = e & 63;
            Ks[r][d] = base[(size_t)r * TRIPLE + D_MODEL + d];
            Vs[r][d] = base[(size_t)r * TRIPLE + 2 * D_MODEL + d];
        }
        __syncthreads();
        for (int t = 0; t < 64; t++) {
            float kv[4], vv[4];
#pragma unroll
            for (int a = 0; a < 4; a++) kv[a] = Ks[t][ti + a];
#pragma unroll
            for (int b = 0; b < 4; b++) vv[b] = Vs[t][tj + b];
#pragma unroll
            for (int a = 0; a < 4; a++)
#pragma unroll
                for (int b = 0; b < 4; b++)
                    acc[a][b] = fmaf(kv[a], vv[b], acc[a][b]);
        }
        if (tid < HD) {
            for (int t = 0; t < 64; t++) ksum_acc += Ks[t][tid];
        }
        __syncthreads();
    }

    float* st = g_state + (size_t)(h * NCHUNK + c) * HD * HD;
#pragma unroll
    for (int a = 0; a < 4; a++)
#pragma unroll
        for (int b = 0; b < 4; b++)
            st[(ti + a) * HD + tj + b] = acc[a][b];
    if (tid < HD) g_ksum[(h * NCHUNK + c) * HD + tid] = ksum_acc;
}

// ---------------- K3: inclusive prefix over chunks (per head) ----------------
__global__ __launch_bounds__(256) void prefix_kernel()
{
    const int h = blockIdx.x;
    const int tid = threadIdx.x;
    for (int e = tid; e < HD * HD; e += 256) {
        float run = 0.f;
        for (int c = 0; c < NCHUNK; c++) {
            float* p = g_state + (size_t)(h * NCHUNK + c) * HD * HD + e;
            run += *p;
            *p = run;
        }
    }
    if (tid < HD) {
        float run = 0.f;
        for (int c = 0; c < NCHUNK; c++) {
            float* p = g_ksum + (h * NCHUNK + c) * HD + tid;
            run += *p;
            *p = run;
        }
    }
}

// ---------------- K4: per-(head, chunk) output ----------------
// out[i] = ( phi_q[i] @ S_prev + sum_{t<=i} (phi_q[i].phi_k[t]) v[t] )
//        / ( phi_q[i].kprev + sum_{t<=i} phi_q[i].phi_k[t] + eps )
// Thread mapping: 256 threads = 128 rows x 2 halves of the 64 output dims.
__global__ __launch_bounds__(256) void chunk_out_kernel()
{
    extern __shared__ float sm[];
    float* Qs = sm;                         // [128][65] padded
    float* Ks = Qs + CHUNK * 65;            // [128][64]
    float* Vs = Ks + CHUNK * HD;            // [128][64]
    float* Sp = Vs + CHUNK * HD;            // [64][64]
    float* kp = Sp + HD * HD;               // [64]

    const int c = blockIdx.x, h = blockIdx.y;
    const int tid = threadIdx.x;
    const int s0 = c * CHUNK;
    const float* base = g_qkv + (size_t)s0 * TRIPLE + h * HD;

    for (int e = tid; e < CHUNK * HD; e += 256) {
        const int r = e >> 6, d = e & 63;
        Qs[r * 65 + d] = base[(size_t)r * TRIPLE + d];
        Ks[e] = base[(size_t)r * TRIPLE + D_MODEL + d];
        Vs[e] = base[(size_t)r * TRIPLE + 2 * D_MODEL + d];
    }
    if (c > 0) {
        const float* st = g_state + (size_t)(h * NCHUNK + c - 1) * HD * HD;
        for (int e = tid; e < HD * HD; e += 256) Sp[e] = st[e];
        if (tid < HD) kp[tid] = g_ksum[(h * NCHUNK + c - 1) * HD + tid];
    } else {
        for (int e = tid; e < HD * HD; e += 256) Sp[e] = 0.f;
        if (tid < HD) kp[tid] = 0.f;
    }
    __syncthreads();

    const int i  = tid & 127;
    const int j0 = (tid >> 7) * 32;

    // q row in registers (fully unrolled -> static indices, no spill)
    float qreg[HD];
#pragma unroll
    for (int d = 0; d < HD; d++) qreg[d] = Qs[i * 65 + d];

    float acc[32];
#pragma unroll
    for (int j = 0; j < 32; j++) acc[j] = 0.f;
    float denom = EPSV;

    // inter-chunk: q @ S_prev  (q read from smem: loop index is dynamic)
    for (int d = 0; d < HD; d++) {
        const float qd = Qs[i * 65 + d];
        denom = fmaf(qd, kp[d], denom);
        const float* sprow = Sp + d * HD + j0;
#pragma unroll
        for (int j = 0; j < 32; j++) acc[j] = fmaf(qd, sprow[j], acc[j]);
    }

    // intra-chunk causal
    for (int t = 0; t <= i; t++) {
        const float* krow = Ks + t * HD;
        float a = 0.f;
#pragma unroll
        for (int d = 0; d < HD; d++) a = fmaf(qreg[d], krow[d], a);
        denom += a;
        const float* vrow = Vs + t * HD + j0;
#pragma unroll
        for (int j = 0; j < 32; j++) acc[j] = fmaf(a, vrow[j], acc[j]);
    }

    const float inv = 1.f / denom;
    float* orow = g_attn + (size_t)(s0 + i) * D_MODEL + h * HD + j0;
#pragma unroll
    for (int j = 0; j < 32; j += 4) {
        float4 v;
        v.x = acc[j + 0] * inv;
        v.y = acc[j + 1] * inv;
        v.z = acc[j + 2] * inv;
        v.w = acc[j + 3] * inv;
        *reinterpret_cast<float4*>(orow + j) = v;
    }
}

// ---------------- launch ----------------
static const int kOutSmemBytes = (CHUNK * 65 + CHUNK * HD * 2 + HD * HD + HD) * (int)sizeof(float); // 115456

extern "C" void kernel_launch(void* const* d_in, const int* in_sizes, int n_in,
                              void* d_out, int out_size)
{
    (void)in_sizes; (void)n_in; (void)out_size;
    const float* x    = (const float*)d_in[0];
    // d_in[1] is the causal mask (implicit in the algorithm)
    const float* Wqkv = (const float*)d_in[2];
    const float* Wout = (const float*)d_in[3];
    float* out = (float*)d_out;

    float* qkv_ptr = nullptr;
    float* attn_ptr = nullptr;
    cudaGetSymbolAddress((void**)&qkv_ptr, g_qkv);
    cudaGetSymbolAddress((void**)&attn_ptr, g_attn);

    cudaFuncSetAttribute(chunk_out_kernel,
                         cudaFuncAttributeMaxDynamicSharedMemorySize, kOutSmemBytes);

    // K1: qkv = x @ W_qkv, feature map applied to q,k columns (< 2048)
    dim3 g1(TRIPLE / 128, S_LEN / 128);
    sgemm_kernel<<<g1, 256>>>(x, Wqkv, qkv_ptr, S_LEN, TRIPLE, D_MODEL, 2 * D_MODEL);

    // K2: per-chunk local states
    dim3 g2(NCHUNK, H_NUM);
    chunk_state_kernel<<<g2, 256>>>();

    // K3: inclusive prefix over chunks
    prefix_kernel<<<H_NUM, 256>>>();

    // K4: chunk outputs
    chunk_out_kernel<<<g2, 256, kOutSmemBytes>>>();

    // K5: out = attn @ W_out
    dim3 g3(D_MODEL / 128, S_LEN / 128);
    sgemm_kernel<<<g3, 256>>>(attn_ptr, Wout, out, S_LEN, D_MODEL, D_MODEL, 0);
}

// round 3
// speedup vs baseline: 2.0533x; 2.0533x over previous
#include <cuda_runtime.h>
#include <cuda_bf16.h>
#include <math.h>
#include <stdint.h>

#define S_LEN   2048
#define D_MODEL 1024
#define TRIPLE  (3 * D_MODEL)
#define H_NUM   16
#define HD      64
#define CHUNK   128
#define NCHUNK  (S_LEN / CHUNK)   // 16
#define EPSV    1e-6f

// ---------------- scratch (no allocations allowed) ----------------
__device__ float g_qkv[(size_t)S_LEN * TRIPLE];              // [phi(q) | phi(k) | v] fp32
__device__ float g_state[(size_t)H_NUM * NCHUNK * HD * HD];
__device__ float g_ksum[H_NUM * NCHUNK * HD];

// bf16 hi/lo split operands for tensor-core GEMMs
__device__ __nv_bfloat16 g_x_hi[(size_t)S_LEN * D_MODEL];
__device__ __nv_bfloat16 g_x_lo[(size_t)S_LEN * D_MODEL];
__device__ __nv_bfloat16 g_wq_hi[(size_t)TRIPLE * D_MODEL];   // W_qkv^T [3072,1024]
__device__ __nv_bfloat16 g_wq_lo[(size_t)TRIPLE * D_MODEL];
__device__ __nv_bfloat16 g_wo_hi[(size_t)D_MODEL * D_MODEL];  // W_out^T [1024,1024]
__device__ __nv_bfloat16 g_wo_lo[(size_t)D_MODEL * D_MODEL];
__device__ __nv_bfloat16 g_at_hi[(size_t)S_LEN * D_MODEL];    // attn output hi/lo
__device__ __nv_bfloat16 g_at_lo[(size_t)S_LEN * D_MODEL];

__device__ __forceinline__ float phi_fn(float x) {
    return x > 0.f ? x + 1.f : expf(x);
}

__device__ __forceinline__ uint32_t smem_u32(const void* p) {
    uint32_t a;
    asm("{ .reg .u64 t; cvta.to.shared.u64 t, %1; cvt.u32.u64 %0, t; }" : "=r"(a) : "l"(p));
    return a;
}
__device__ __forceinline__ void cp16(uint32_t s, const void* g) {
    asm volatile("cp.async.cg.shared.global [%0], [%1], 16;" :: "r"(s), "l"(g) : "memory");
}
#define CP_COMMIT() asm volatile("cp.async.commit_group;" ::: "memory")
#define CP_WAIT1()  asm volatile("cp.async.wait_group 1;" ::: "memory")

__device__ __forceinline__ void ldm_x4(uint32_t addr, uint32_t* r) {
    asm volatile("ldmatrix.sync.aligned.m8n8.x4.shared.b16 {%0,%1,%2,%3}, [%4];"
        : "=r"(r[0]), "=r"(r[1]), "=r"(r[2]), "=r"(r[3]) : "r"(addr));
}
__device__ __forceinline__ void mma16816(float* d, const uint32_t* a, uint32_t b0, uint32_t b1) {
    asm volatile("mma.sync.aligned.m16n8k16.row.col.f32.bf16.bf16.f32 "
        "{%0,%1,%2,%3}, {%4,%5,%6,%7}, {%8,%9}, {%0,%1,%2,%3};"
        : "+f"(d[0]), "+f"(d[1]), "+f"(d[2]), "+f"(d[3])
        : "r"(a[0]), "r"(a[1]), "r"(a[2]), "r"(a[3]), "r"(b0), "r"(b1));
}

// ====================== conversion kernels ======================
__global__ __launch_bounds__(256) void conv_hilo_kernel(
    const float* __restrict__ X, __nv_bfloat16* __restrict__ hi, __nv_bfloat16* __restrict__ lo, int n4)
{
    int i = blockIdx.x * 256 + threadIdx.x;
    if (i >= n4) return;
    float4 v = reinterpret_cast<const float4*>(X)[i];
    __nv_bfloat16 h0 = __float2bfloat16(v.x), h1 = __float2bfloat16(v.y);
    __nv_bfloat16 h2 = __float2bfloat16(v.z), h3 = __float2bfloat16(v.w);
    __nv_bfloat16 l0 = __float2bfloat16(v.x - __bfloat162float(h0));
    __nv_bfloat16 l1 = __float2bfloat16(v.y - __bfloat162float(h1));
    __nv_bfloat16 l2 = __float2bfloat16(v.z - __bfloat162float(h2));
    __nv_bfloat16 l3 = __float2bfloat16(v.w - __bfloat162float(h3));
    reinterpret_cast<__nv_bfloat162*>(hi)[i * 2 + 0] = __nv_bfloat162(h0, h1);
    reinterpret_cast<__nv_bfloat162*>(hi)[i * 2 + 1] = __nv_bfloat162(h2, h3);
    reinterpret_cast<__nv_bfloat162*>(lo)[i * 2 + 0] = __nv_bfloat162(l0, l1);
    reinterpret_cast<__nv_bfloat162*>(lo)[i * 2 + 1] = __nv_bfloat162(l2, l3);
}

// transpose + hi/lo split: W [R rows, Ccols] -> T[Ccols, R] (hi, lo)
__global__ __launch_bounds__(256) void transpose_hilo_kernel(
    const float* __restrict__ W, __nv_bfloat16* __restrict__ Thi, __nv_bfloat16* __restrict__ Tlo,
    int R, int Ccols)
{
    __shared__ float t[32][33];
    const int tx = threadIdx.x, ty = threadIdx.y;   // 32 x 8
    const int bx = blockIdx.x, by = blockIdx.y;
#pragma unroll
    for (int j = 0; j < 4; j++) {
        int r = by * 32 + ty + j * 8;
        int c = bx * 32 + tx;
        t[ty + j * 8][tx] = W[(size_t)r * Ccols + c];
    }
    __syncthreads();
#pragma unroll
    for (int j = 0; j < 4; j++) {
        int n = bx * 32 + ty + j * 8;
        int k = by * 32 + tx;
        float v = t[tx][ty + j * 8];
        __nv_bfloat16 h = __float2bfloat16(v);
        __nv_bfloat16 l = __float2bfloat16(v - __bfloat162float(h));
        Thi[(size_t)n * R + k] = h;
        Tlo[(size_t)n * R + k] = l;
    }
}

// ====================== mma.sync GEMM: C = A @ B^T, 3-way bf16 split ======================
// A_{hi,lo}: [M,1024] bf16 row-major;  B_{hi,lo}: [N,1024] bf16 row-major (pre-transposed W)
// C: [M,N] fp32; phi applied to columns < phi_cols (tile-uniform).
#define BK        32
#define NKB       (D_MODEL / BK)         // 32
#define ROW_B     80                      // smem row stride bytes (32 bf16 data + 16B pad)
#define TILE_B    (128 * ROW_B)           // 10240
#define STAGE_B   (4 * TILE_B)            // Ah|Al|Bh|Bl = 40960
#define NSTAGE    3
#define GEMM_SMEM (NSTAGE * STAGE_B)      // 122880

__device__ __forceinline__ void issue_stage(
    uint32_t sbase, const __nv_bfloat16* pAh, const __nv_bfloat16* pAl,
    const __nv_bfloat16* pBh, const __nv_bfloat16* pBl, int k0, int tid)
{
    const __nv_bfloat16* srcs[4] = { pAh, pAl, pBh, pBl };
#pragma unroll
    for (int t = 0; t < 4; t++) {
#pragma unroll
        for (int c = 0; c < 2; c++) {
            int w = tid + 256 * c;           // 0..511 chunks of 16B
            int row = w >> 2, seg = w & 3;
            uint32_t s = sbase + (uint32_t)t * TILE_B + (uint32_t)row * ROW_B + (uint32_t)seg * 16;
            cp16(s, srcs[t] + (size_t)row * D_MODEL + k0 + seg * 8);
        }
    }
}

__global__ __launch_bounds__(256, 1) void gemm3_mma_kernel(
    const __nv_bfloat16* __restrict__ Ahi, const __nv_bfloat16* __restrict__ Alo,
    const __nv_bfloat16* __restrict__ Bhi, const __nv_bfloat16* __restrict__ Blo,
    float* __restrict__ C, int N, int phi_cols)
{
    extern __shared__ char smem_raw[];
    const uint32_t sb = smem_u32(smem_raw);
    const int tid = threadIdx.x;
    const int wid = tid >> 5, lane = tid & 31;
    const int warp_m = wid & 3;     // 4 warps along M, 32 rows each
    const int warp_n = wid >> 2;    // 2 warps along N, 64 cols each
    const int bm = blockIdx.y, bn = blockIdx.x;

    const __nv_bfloat16* pAh = Ahi + (size_t)bm * 128 * D_MODEL;
    const __nv_bfloat16* pAl = Alo + (size_t)bm * 128 * D_MODEL;
    const __nv_bfloat16* pBh = Bhi + (size_t)bn * 128 * D_MODEL;
    const __nv_bfloat16* pBl = Blo + (size_t)bn * 128 * D_MODEL;

    float acc[2][8][4];
#pragma unroll
    for (int mt = 0; mt < 2; mt++)
#pragma unroll
        for (int q = 0; q < 8; q++)
#pragma unroll
            for (int e = 0; e < 4; e++) acc[mt][q][e] = 0.f;

    // ldmatrix lane -> (row, byte) mapping
    const int aRow  = warp_m * 32 + (lane & 7) + ((lane >> 3) & 1) * 8;  // + mt*16
    const int aByte = (lane >> 4) * 16;                                   // + ks*32
    const int bRow  = warp_n * 64 + (lane & 7) + (lane >> 4) * 8;         // + p*16
    const int bByte = ((lane >> 3) & 1) * 16;                             // + ks*32

    issue_stage(sb + 0 * STAGE_B, pAh, pAl, pBh, pBl, 0, tid);  CP_COMMIT();
    issue_stage(sb + 1 * STAGE_B, pAh, pAl, pBh, pBl, BK, tid); CP_COMMIT();

    for (int kb = 0; kb < NKB; kb++) {
        CP_WAIT1();
        __syncthreads();
        if (kb + 2 < NKB)
            issue_stage(sb + ((kb + 2) % NSTAGE) * STAGE_B, pAh, pAl, pBh, pBl, (kb + 2) * BK, tid);
        CP_COMMIT();   // always commit (possibly empty) to keep group accounting exact

        const uint32_t st = sb + (kb % NSTAGE) * STAGE_B;
#pragma unroll
        for (int ks = 0; ks < 2; ks++) {
            uint32_t ah[2][4], al[2][4], bh[4][4], bl[4][4];
#pragma unroll
            for (int mt = 0; mt < 2; mt++) {
                const uint32_t ro = (uint32_t)(aRow + mt * 16) * ROW_B + aByte + ks * 32;
                ldm_x4(st + 0 * TILE_B + ro, ah[mt]);
                ldm_x4(st + 1 * TILE_B + ro, al[mt]);
            }
#pragma unroll
            for (int p = 0; p < 4; p++) {
                const uint32_t ro = (uint32_t)(bRow + p * 16) * ROW_B + bByte + ks * 32;
                ldm_x4(st + 2 * TILE_B + ro, bh[p]);
                ldm_x4(st + 3 * TILE_B + ro, bl[p]);
            }
#pragma unroll
            for (int mt = 0; mt < 2; mt++)
#pragma unroll
                for (int p = 0; p < 4; p++)
#pragma unroll
                    for (int h = 0; h < 2; h++) {
                        const int q = p * 2 + h;
                        const uint32_t bh0 = bh[p][h * 2], bh1 = bh[p][h * 2 + 1];
                        const uint32_t bl0 = bl[p][h * 2], bl1 = bl[p][h * 2 + 1];
                        mma16816(acc[mt][q], ah[mt], bh0, bh1);
                        mma16816(acc[mt][q], ah[mt], bl0, bl1);
                        mma16816(acc[mt][q], al[mt], bh0, bh1);
                    }
        }
    }

    // epilogue: phi + store fp32
    const bool ap = (bn * 128) < phi_cols;
    const int r0 = lane >> 2, c0 = (lane & 3) * 2;
#pragma unroll
    for (int mt = 0; mt < 2; mt++) {
        const int row = bm * 128 + warp_m * 32 + mt * 16 + r0;
#pragma unroll
        for (int q = 0; q < 8; q++) {
            const int col = bn * 128 + warp_n * 64 + q * 8 + c0;
            float2 v0 = make_float2(acc[mt][q][0], acc[mt][q][1]);
            float2 v1 = make_float2(acc[mt][q][2], acc[mt][q][3]);
            if (ap) {
                v0.x = phi_fn(v0.x); v0.y = phi_fn(v0.y);
                v1.x = phi_fn(v1.x); v1.y = phi_fn(v1.y);
            }
            *reinterpret_cast<float2*>(C + (size_t)row * N + col)       = v0;
            *reinterpret_cast<float2*>(C + (size_t)(row + 8) * N + col) = v1;
        }
    }
}

// ---------------- K2: per-(head, chunk) local KV state + k-sum ----------------
__global__ __launch_bounds__(256) void chunk_state_kernel()
{
    __shared__ float Ks[64][64];
    __shared__ float Vs[64][64];
    const int c = blockIdx.x, h = blockIdx.y;
    const int tid = threadIdx.x;
    const int ti = (tid >> 4) * 4;
    const int tj = (tid & 15) * 4;

    float acc[4][4];
#pragma unroll
    for (int a = 0; a < 4; a++)
#pragma unroll
        for (int b = 0; b < 4; b++) acc[a][b] = 0.f;
    float ksum_acc = 0.f;

    for (int half = 0; half < 2; half++) {
        const int s0 = c * CHUNK + half * 64;
        const float* base = g_qkv + (size_t)s0 * TRIPLE + h * HD;
        for (int e = tid; e < 64 * HD; e += 256) {
            const int r = e >> 6, d = e & 63;
            Ks[r][d] = base[(size_t)r * TRIPLE + D_MODEL + d];
            Vs[r][d] = base[(size_t)r * TRIPLE + 2 * D_MODEL + d];
        }
        __syncthreads();
        for (int t = 0; t < 64; t++) {
            float kv[4], vv[4];
#pragma unroll
            for (int a = 0; a < 4; a++) kv[a] = Ks[t][ti + a];
#pragma unroll
            for (int b = 0; b < 4; b++) vv[b] = Vs[t][tj + b];
#pragma unroll
            for (int a = 0; a < 4; a++)
#pragma unroll
                for (int b = 0; b < 4; b++)
                    acc[a][b] = fmaf(kv[a], vv[b], acc[a][b]);
        }
        if (tid < HD) {
            for (int t = 0; t < 64; t++) ksum_acc += Ks[t][tid];
        }
        __syncthreads();
    }

    float* st = g_state + (size_t)(h * NCHUNK + c) * HD * HD;
#pragma unroll
    for (int a = 0; a < 4; a++)
#pragma unroll
        for (int b = 0; b < 4; b++)
            st[(ti + a) * HD + tj + b] = acc[a][b];
    if (tid < HD) g_ksum[(h * NCHUNK + c) * HD + tid] = ksum_acc;
}

// ---------------- K3: inclusive prefix over chunks (per head) ----------------
__global__ __launch_bounds__(256) void prefix_kernel()
{
    const int h = blockIdx.x;
    const int tid = threadIdx.x;
    for (int e = tid; e < HD * HD; e += 256) {
        float run = 0.f;
        for (int c = 0; c < NCHUNK; c++) {
            float* p = g_state + (size_t)(h * NCHUNK + c) * HD * HD + e;
            run += *p;
            *p = run;
        }
    }
    if (tid < HD) {
        float run = 0.f;
        for (int c = 0; c < NCHUNK; c++) {
            float* p = g_ksum + (h * NCHUNK + c) * HD + tid;
            run += *p;
            *p = run;
        }
    }
}

// ---------------- K4: per-(head, chunk) output (writes bf16 hi/lo attn) ----------------
__global__ __launch_bounds__(256) void chunk_out_kernel()
{
    extern __shared__ float sm[];
    float* Qs = sm;                         // [128][65] padded
    float* Ks = Qs + CHUNK * 65;            // [128][64]
    float* Vs = Ks + CHUNK * HD;            // [128][64]
    float* Sp = Vs + CHUNK * HD;            // [64][64]
    float* kp = Sp + HD * HD;               // [64]

    const int c = blockIdx.x, h = blockIdx.y;
    const int tid = threadIdx.x;
    const int s0 = c * CHUNK;
    const float* base = g_qkv + (size_t)s0 * TRIPLE + h * HD;

    for (int e = tid; e < CHUNK * HD; e += 256) {
        const int r = e >> 6, d = e & 63;
        Qs[r * 65 + d] = base[(size_t)r * TRIPLE + d];
        Ks[e] = base[(size_t)r * TRIPLE + D_MODEL + d];
        Vs[e] = base[(size_t)r * TRIPLE + 2 * D_MODEL + d];
    }
    if (c > 0) {
        const float* st = g_state + (size_t)(h * NCHUNK + c - 1) * HD * HD;
        for (int e = tid; e < HD * HD; e += 256) Sp[e] = st[e];
        if (tid < HD) kp[tid] = g_ksum[(h * NCHUNK + c - 1) * HD + tid];
    } else {
        for (int e = tid; e < HD * HD; e += 256) Sp[e] = 0.f;
        if (tid < HD) kp[tid] = 0.f;
    }
    __syncthreads();

    const int i  = tid & 127;
    const int j0 = (tid >> 7) * 32;

    float qreg[HD];
#pragma unroll
    for (int d = 0; d < HD; d++) qreg[d] = Qs[i * 65 + d];

    float acc[32];
#pragma unroll
    for (int j = 0; j < 32; j++) acc[j] = 0.f;
    float denom = EPSV;

    for (int d = 0; d < HD; d++) {
        const float qd = Qs[i * 65 + d];
        denom = fmaf(qd, kp[d], denom);
        const float* sprow = Sp + d * HD + j0;
#pragma unroll
        for (int j = 0; j < 32; j++) acc[j] = fmaf(qd, sprow[j], acc[j]);
    }

    for (int t = 0; t <= i; t++) {
        const float* krow = Ks + t * HD;
        float a = 0.f;
#pragma unroll
        for (int d = 0; d < HD; d++) a = fmaf(qreg[d], krow[d], a);
        denom += a;
        const float* vrow = Vs + t * HD + j0;
#pragma unroll
        for (int j = 0; j < 32; j++) acc[j] = fmaf(a, vrow[j], acc[j]);
    }

    const float inv = 1.f / denom;
    const size_t obase = (size_t)(s0 + i) * D_MODEL + h * HD + j0;
    __nv_bfloat162* oh = reinterpret_cast<__nv_bfloat162*>(g_at_hi + obase);
    __nv_bfloat162* ol = reinterpret_cast<__nv_bfloat162*>(g_at_lo + obase);
#pragma unroll
    for (int j = 0; j < 32; j += 2) {
        float v0 = acc[j] * inv, v1 = acc[j + 1] * inv;
        __nv_bfloat16 h0 = __float2bfloat16(v0), h1 = __float2bfloat16(v1);
        __nv_bfloat16 l0 = __float2bfloat16(v0 - __bfloat162float(h0));
        __nv_bfloat16 l1 = __float2bfloat16(v1 - __bfloat162float(h1));
        oh[j >> 1] = __nv_bfloat162(h0, h1);
        ol[j >> 1] = __nv_bfloat162(l0, l1);
    }
}

// ---------------- launch ----------------
static const int kOutSmemBytes = (CHUNK * 65 + CHUNK * HD * 2 + HD * HD + HD) * (int)sizeof(float);

extern "C" void kernel_launch(void* const* d_in, const int* in_sizes, int n_in,
                              void* d_out, int out_size)
{
    (void)in_sizes; (void)n_in; (void)out_size;
    const float* x    = (const float*)d_in[0];
    const float* Wqkv = (const float*)d_in[2];
    const float* Wout = (const float*)d_in[3];
    float* out = (float*)d_out;

    float* qkv_ptr;
    __nv_bfloat16 *xh, *xl, *wqh, *wql, *woh, *wol, *ath, *atl;
    cudaGetSymbolAddress((void**)&qkv_ptr, g_qkv);
    cudaGetSymbolAddress((void**)&xh, g_x_hi);
    cudaGetSymbolAddress((void**)&xl, g_x_lo);
    cudaGetSymbolAddress((void**)&wqh, g_wq_hi);
    cudaGetSymbolAddress((void**)&wql, g_wq_lo);
    cudaGetSymbolAddress((void**)&woh, g_wo_hi);
    cudaGetSymbolAddress((void**)&wol, g_wo_lo);
    cudaGetSymbolAddress((void**)&ath, g_at_hi);
    cudaGetSymbolAddress((void**)&atl, g_at_lo);

    cudaFuncSetAttribute(chunk_out_kernel,
                         cudaFuncAttributeMaxDynamicSharedMemorySize, kOutSmemBytes);
    cudaFuncSetAttribute(gemm3_mma_kernel,
                         cudaFuncAttributeMaxDynamicSharedMemorySize, GEMM_SMEM);

    // conversions
    conv_hilo_kernel<<<(S_LEN * D_MODEL / 4 + 255) / 256, 256>>>(x, xh, xl, S_LEN * D_MODEL / 4);
    {
        dim3 b(32, 8);
        dim3 gq(TRIPLE / 32, D_MODEL / 32);
        transpose_hilo_kernel<<<gq, b>>>(Wqkv, wqh, wql, D_MODEL, TRIPLE);
        dim3 go(D_MODEL / 32, D_MODEL / 32);
        transpose_hilo_kernel<<<go, b>>>(Wout, woh, wol, D_MODEL, D_MODEL);
    }

    // K1: qkv = x @ W_qkv (HMMA tensor cores), phi on first 2048 cols
    {
        dim3 g(TRIPLE / 128, S_LEN / 128);
        gemm3_mma_kernel<<<g, 256, GEMM_SMEM>>>(xh, xl, wqh, wql, qkv_ptr, TRIPLE, 2 * D_MODEL);
    }

    // K2/K3/K4
    dim3 g2(NCHUNK, H_NUM);
    chunk_state_kernel<<<g2, 256>>>();
    prefix_kernel<<<H_NUM, 256>>>();
    chunk_out_kernel<<<g2, 256, kOutSmemBytes>>>();

    // K5: out = attn @ W_out (HMMA tensor cores)
    {
        dim3 g(D_MODEL / 128, S_LEN / 128);
        gemm3_mma_kernel<<<g, 256, GEMM_SMEM>>>(ath, atl, woh, wol, out, D_MODEL, 0);
    }
}

// round 4
// speedup vs baseline: 2.3018x; 1.1210x over previous
#include <cuda_runtime.h>
#include <cuda_bf16.h>
#include <math.h>
#include <stdint.h>

#define S_LEN   2048
#define D_MODEL 1024
#define TRIPLE  (3 * D_MODEL)
#define H_NUM   16
#define HD      64
#define CHUNK   64
#define NCHUNK  (S_LEN / CHUNK)   // 32
#define EPSV    1e-6f

// ---------------- scratch (no allocations allowed) ----------------
__device__ float g_qkv[(size_t)S_LEN * TRIPLE];              // [phi(q) | phi(k) | v] fp32
__device__ float g_state[(size_t)H_NUM * NCHUNK * HD * HD];
__device__ float g_ksum[H_NUM * NCHUNK * HD];

// bf16 hi/lo split operands for tensor-core GEMMs
__device__ __nv_bfloat16 g_x_hi[(size_t)S_LEN * D_MODEL];
__device__ __nv_bfloat16 g_x_lo[(size_t)S_LEN * D_MODEL];
__device__ __nv_bfloat16 g_wq_hi[(size_t)TRIPLE * D_MODEL];   // W_qkv^T [3072,1024]
__device__ __nv_bfloat16 g_wq_lo[(size_t)TRIPLE * D_MODEL];
__device__ __nv_bfloat16 g_wo_hi[(size_t)D_MODEL * D_MODEL];  // W_out^T [1024,1024]
__device__ __nv_bfloat16 g_wo_lo[(size_t)D_MODEL * D_MODEL];
__device__ __nv_bfloat16 g_at_hi[(size_t)S_LEN * D_MODEL];    // attn output hi/lo
__device__ __nv_bfloat16 g_at_lo[(size_t)S_LEN * D_MODEL];

__device__ __forceinline__ float phi_fn(float x) {
    return x > 0.f ? x + 1.f : expf(x);
}

__device__ __forceinline__ uint32_t smem_u32(const void* p) {
    uint32_t a;
    asm("{ .reg .u64 t; cvta.to.shared.u64 t, %1; cvt.u32.u64 %0, t; }" : "=r"(a) : "l"(p));
    return a;
}
__device__ __forceinline__ void cp16(uint32_t s, const void* g) {
    asm volatile("cp.async.cg.shared.global [%0], [%1], 16;" :: "r"(s), "l"(g) : "memory");
}
#define CP_COMMIT() asm volatile("cp.async.commit_group;" ::: "memory")
#define CP_WAIT1()  asm volatile("cp.async.wait_group 1;" ::: "memory")

__device__ __forceinline__ void ldm_x4(uint32_t addr, uint32_t* r) {
    asm volatile("ldmatrix.sync.aligned.m8n8.x4.shared.b16 {%0,%1,%2,%3}, [%4];"
        : "=r"(r[0]), "=r"(r[1]), "=r"(r[2]), "=r"(r[3]) : "r"(addr));
}
__device__ __forceinline__ void mma16816(float* d, const uint32_t* a, uint32_t b0, uint32_t b1) {
    asm volatile("mma.sync.aligned.m16n8k16.row.col.f32.bf16.bf16.f32 "
        "{%0,%1,%2,%3}, {%4,%5,%6,%7}, {%8,%9}, {%0,%1,%2,%3};"
        : "+f"(d[0]), "+f"(d[1]), "+f"(d[2]), "+f"(d[3])
        : "r"(a[0]), "r"(a[1]), "r"(a[2]), "r"(a[3]), "r"(b0), "r"(b1));
}

// ====================== conversion kernels ======================
__global__ __launch_bounds__(256) void conv_hilo_kernel(
    const float* __restrict__ X, __nv_bfloat16* __restrict__ hi, __nv_bfloat16* __restrict__ lo, int n4)
{
    int i = blockIdx.x * 256 + threadIdx.x;
    if (i >= n4) return;
    float4 v = reinterpret_cast<const float4*>(X)[i];
    __nv_bfloat16 h0 = __float2bfloat16(v.x), h1 = __float2bfloat16(v.y);
    __nv_bfloat16 h2 = __float2bfloat16(v.z), h3 = __float2bfloat16(v.w);
    __nv_bfloat16 l0 = __float2bfloat16(v.x - __bfloat162float(h0));
    __nv_bfloat16 l1 = __float2bfloat16(v.y - __bfloat162float(h1));
    __nv_bfloat16 l2 = __float2bfloat16(v.z - __bfloat162float(h2));
    __nv_bfloat16 l3 = __float2bfloat16(v.w - __bfloat162float(h3));
    reinterpret_cast<__nv_bfloat162*>(hi)[i * 2 + 0] = __nv_bfloat162(h0, h1);
    reinterpret_cast<__nv_bfloat162*>(hi)[i * 2 + 1] = __nv_bfloat162(h2, h3);
    reinterpret_cast<__nv_bfloat162*>(lo)[i * 2 + 0] = __nv_bfloat162(l0, l1);
    reinterpret_cast<__nv_bfloat162*>(lo)[i * 2 + 1] = __nv_bfloat162(l2, l3);
}

// transpose + hi/lo split: W [R rows, Ccols] -> T[Ccols, R] (hi, lo)
__global__ __launch_bounds__(256) void transpose_hilo_kernel(
    const float* __restrict__ W, __nv_bfloat16* __restrict__ Thi, __nv_bfloat16* __restrict__ Tlo,
    int R, int Ccols)
{
    __shared__ float t[32][33];
    const int tx = threadIdx.x, ty = threadIdx.y;   // 32 x 8
    const int bx = blockIdx.x, by = blockIdx.y;
#pragma unroll
    for (int j = 0; j < 4; j++) {
        int r = by * 32 + ty + j * 8;
        int c = bx * 32 + tx;
        t[ty + j * 8][tx] = W[(size_t)r * Ccols + c];
    }
    __syncthreads();
#pragma unroll
    for (int j = 0; j < 4; j++) {
        int n = bx * 32 + ty + j * 8;
        int k = by * 32 + tx;
        float v = t[tx][ty + j * 8];
        __nv_bfloat16 h = __float2bfloat16(v);
        __nv_bfloat16 l = __float2bfloat16(v - __bfloat162float(h));
        Thi[(size_t)n * R + k] = h;
        Tlo[(size_t)n * R + k] = l;
    }
}

// ====================== mma.sync GEMM: C = A @ B^T, 3-way bf16 split ======================
// 2-stage pipeline, 2 CTAs/SM for tensor-pipe overlap.
#define BK        32
#define NKB       (D_MODEL / BK)         // 32
#define ROW_B     80                      // smem row stride bytes (32 bf16 data + 16B pad)
#define TILE_B    (128 * ROW_B)           // 10240
#define STAGE_B   (4 * TILE_B)            // Ah|Al|Bh|Bl = 40960
#define NSTAGE    2
#define GEMM_SMEM (NSTAGE * STAGE_B)      // 81920

__device__ __forceinline__ void issue_stage(
    uint32_t sbase, const __nv_bfloat16* pAh, const __nv_bfloat16* pAl,
    const __nv_bfloat16* pBh, const __nv_bfloat16* pBl, int k0, int tid)
{
    const __nv_bfloat16* srcs[4] = { pAh, pAl, pBh, pBl };
#pragma unroll
    for (int t = 0; t < 4; t++) {
#pragma unroll
        for (int c = 0; c < 2; c++) {
            int w = tid + 256 * c;           // 0..511 chunks of 16B
            int row = w >> 2, seg = w & 3;
            uint32_t s = sbase + (uint32_t)t * TILE_B + (uint32_t)row * ROW_B + (uint32_t)seg * 16;
            cp16(s, srcs[t] + (size_t)row * D_MODEL + k0 + seg * 8);
        }
    }
}

__global__ __launch_bounds__(256, 2) void gemm3_mma_kernel(
    const __nv_bfloat16* __restrict__ Ahi, const __nv_bfloat16* __restrict__ Alo,
    const __nv_bfloat16* __restrict__ Bhi, const __nv_bfloat16* __restrict__ Blo,
    float* __restrict__ C, int N, int phi_cols)
{
    extern __shared__ char smem_raw[];
    const uint32_t sb = smem_u32(smem_raw);
    const int tid = threadIdx.x;
    const int wid = tid >> 5, lane = tid & 31;
    const int warp_m = wid & 3;     // 4 warps along M, 32 rows each
    const int warp_n = wid >> 2;    // 2 warps along N, 64 cols each
    const int bm = blockIdx.y, bn = blockIdx.x;

    const __nv_bfloat16* pAh = Ahi + (size_t)bm * 128 * D_MODEL;
    const __nv_bfloat16* pAl = Alo + (size_t)bm * 128 * D_MODEL;
    const __nv_bfloat16* pBh = Bhi + (size_t)bn * 128 * D_MODEL;
    const __nv_bfloat16* pBl = Blo + (size_t)bn * 128 * D_MODEL;

    float acc[2][8][4];
#pragma unroll
    for (int mt = 0; mt < 2; mt++)
#pragma unroll
        for (int q = 0; q < 8; q++)
#pragma unroll
            for (int e = 0; e < 4; e++) acc[mt][q][e] = 0.f;

    // ldmatrix lane -> (row, byte) mapping
    const int aRow  = warp_m * 32 + (lane & 7) + ((lane >> 3) & 1) * 8;  // + mt*16
    const int aByte = (lane >> 4) * 16;                                   // + ks*32
    const int bRow  = warp_n * 64 + (lane & 7) + (lane >> 4) * 8;         // + p*16
    const int bByte = ((lane >> 3) & 1) * 16;                             // + ks*32

    issue_stage(sb + 0 * STAGE_B, pAh, pAl, pBh, pBl, 0, tid);  CP_COMMIT();
    issue_stage(sb + 1 * STAGE_B, pAh, pAl, pBh, pBl, BK, tid); CP_COMMIT();

    for (int kb = 0; kb < NKB; kb++) {
        CP_WAIT1();              // stage kb resident
        __syncthreads();

        const uint32_t st = sb + (kb & 1) * STAGE_B;
#pragma unroll
        for (int ks = 0; ks < 2; ks++) {
            uint32_t ah[2][4], al[2][4];
#pragma unroll
            for (int mt = 0; mt < 2; mt++) {
                const uint32_t ro = (uint32_t)(aRow + mt * 16) * ROW_B + aByte + ks * 32;
                ldm_x4(st + 0 * TILE_B + ro, ah[mt]);
                ldm_x4(st + 1 * TILE_B + ro, al[mt]);
            }
#pragma unroll
            for (int p = 0; p < 4; p++) {
                uint32_t bh[4], bl[4];
                const uint32_t ro = (uint32_t)(bRow + p * 16) * ROW_B + bByte + ks * 32;
                ldm_x4(st + 2 * TILE_B + ro, bh);
                ldm_x4(st + 3 * TILE_B + ro, bl);
#pragma unroll
                for (int mt = 0; mt < 2; mt++)
#pragma unroll
                    for (int h = 0; h < 2; h++) {
                        const int q = p * 2 + h;
                        mma16816(acc[mt][q], ah[mt], bh[h * 2], bh[h * 2 + 1]);
                        mma16816(acc[mt][q], ah[mt], bl[h * 2], bl[h * 2 + 1]);
                        mma16816(acc[mt][q], al[mt], bh[h * 2], bh[h * 2 + 1]);
                    }
            }
        }

        __syncthreads();         // all warps done reading this stage
        if (kb + 2 < NKB)
            issue_stage(st, pAh, pAl, pBh, pBl, (kb + 2) * BK, tid);
        CP_COMMIT();             // always commit (possibly empty) for exact accounting
    }

    // epilogue: phi + store fp32
    const bool ap = (bn * 128) < phi_cols;
    const int r0 = lane >> 2, c0 = (lane & 3) * 2;
#pragma unroll
    for (int mt = 0; mt < 2; mt++) {
        const int row = bm * 128 + warp_m * 32 + mt * 16 + r0;
#pragma unroll
        for (int q = 0; q < 8; q++) {
            const int col = bn * 128 + warp_n * 64 + q * 8 + c0;
            float2 v0 = make_float2(acc[mt][q][0], acc[mt][q][1]);
            float2 v1 = make_float2(acc[mt][q][2], acc[mt][q][3]);
            if (ap) {
                v0.x = phi_fn(v0.x); v0.y = phi_fn(v0.y);
                v1.x = phi_fn(v1.x); v1.y = phi_fn(v1.y);
            }
            *reinterpret_cast<float2*>(C + (size_t)row * N + col)       = v0;
            *reinterpret_cast<float2*>(C + (size_t)(row + 8) * N + col) = v1;
        }
    }
}

// ---------------- K2: per-(head, chunk) local KV state + k-sum (CHUNK=64) ----------------
__global__ __launch_bounds__(256) void chunk_state_kernel()
{
    __shared__ float Ks[64][64];
    __shared__ float Vs[64][64];
    const int c = blockIdx.x, h = blockIdx.y;
    const int tid = threadIdx.x;
    const int ti = (tid >> 4) * 4;
    const int tj = (tid & 15) * 4;

    float acc[4][4];
#pragma unroll
    for (int a = 0; a < 4; a++)
#pragma unroll
        for (int b = 0; b < 4; b++) acc[a][b] = 0.f;
    float ksum_acc = 0.f;

    const int s0 = c * CHUNK;
    const float* base = g_qkv + (size_t)s0 * TRIPLE + h * HD;
    for (int e = tid; e < 64 * HD; e += 256) {
        const int r = e >> 6, d = e & 63;
        Ks[r][d] = base[(size_t)r * TRIPLE + D_MODEL + d];
        Vs[r][d] = base[(size_t)r * TRIPLE + 2 * D_MODEL + d];
    }
    __syncthreads();
    for (int t = 0; t < 64; t++) {
        float kv[4], vv[4];
#pragma unroll
        for (int a = 0; a < 4; a++) kv[a] = Ks[t][ti + a];
#pragma unroll
        for (int b = 0; b < 4; b++) vv[b] = Vs[t][tj + b];
#pragma unroll
        for (int a = 0; a < 4; a++)
#pragma unroll
            for (int b = 0; b < 4; b++)
                acc[a][b] = fmaf(kv[a], vv[b], acc[a][b]);
    }
    if (tid < HD) {
        for (int t = 0; t < 64; t++) ksum_acc += Ks[t][tid];
    }

    float* st = g_state + (size_t)(h * NCHUNK + c) * HD * HD;
#pragma unroll
    for (int a = 0; a < 4; a++)
#pragma unroll
        for (int b = 0; b < 4; b++)
            st[(ti + a) * HD + tj + b] = acc[a][b];
    if (tid < HD) g_ksum[(h * NCHUNK + c) * HD + tid] = ksum_acc;
}

// ---------------- K3: inclusive prefix over chunks (per head) ----------------
__global__ __launch_bounds__(256) void prefix_kernel()
{
    const int h = blockIdx.x;
    const int tid = threadIdx.x;
    for (int e = tid; e < HD * HD; e += 256) {
        float run = 0.f;
        for (int c = 0; c < NCHUNK; c++) {
            float* p = g_state + (size_t)(h * NCHUNK + c) * HD * HD + e;
            run += *p;
            *p = run;
        }
    }
    if (tid < HD) {
        float run = 0.f;
        for (int c = 0; c < NCHUNK; c++) {
            float* p = g_ksum + (h * NCHUNK + c) * HD + tid;
            run += *p;
            *p = run;
        }
    }
}

// ---------------- K4: per-(head, chunk=64) output (writes bf16 hi/lo attn) ----------------
// 256 threads = 64 rows x 4 column-groups of 16.
__global__ __launch_bounds__(256) void chunk_out_kernel()
{
    extern __shared__ float sm[];
    float* Qs = sm;                         // [64][65] padded
    float* Ks = Qs + CHUNK * 65;            // [64][64]
    float* Vs = Ks + CHUNK * HD;            // [64][64]
    float* Sp = Vs + CHUNK * HD;            // [64][64]
    float* kp = Sp + HD * HD;               // [64]

    const int c = blockIdx.x, h = blockIdx.y;
    const int tid = threadIdx.x;
    const int s0 = c * CHUNK;
    const float* base = g_qkv + (size_t)s0 * TRIPLE + h * HD;

    for (int e = tid; e < CHUNK * HD; e += 256) {
        const int r = e >> 6, d = e & 63;
        Qs[r * 65 + d] = base[(size_t)r * TRIPLE + d];
        Ks[e] = base[(size_t)r * TRIPLE + D_MODEL + d];
        Vs[e] = base[(size_t)r * TRIPLE + 2 * D_MODEL + d];
    }
    if (c > 0) {
        const float* st = g_state + (size_t)(h * NCHUNK + c - 1) * HD * HD;
        for (int e = tid; e < HD * HD; e += 256) Sp[e] = st[e];
        if (tid < HD) kp[tid] = g_ksum[(h * NCHUNK + c - 1) * HD + tid];
    } else {
        for (int e = tid; e < HD * HD; e += 256) Sp[e] = 0.f;
        if (tid < HD) kp[tid] = 0.f;
    }
    __syncthreads();

    const int i  = tid & 63;
    const int j0 = (tid >> 6) * 16;

    float qreg[HD];
#pragma unroll
    for (int d = 0; d < HD; d++) qreg[d] = Qs[i * 65 + d];

    float acc[16];
#pragma unroll
    for (int j = 0; j < 16; j++) acc[j] = 0.f;
    float denom = EPSV;

    // inter-chunk: q @ S_prev
    for (int d = 0; d < HD; d++) {
        const float qd = Qs[i * 65 + d];
        denom = fmaf(qd, kp[d], denom);
        const float* sprow = Sp + d * HD + j0;
#pragma unroll
        for (int j = 0; j < 16; j++) acc[j] = fmaf(qd, sprow[j], acc[j]);
    }

    // intra-chunk causal
    for (int t = 0; t <= i; t++) {
        const float* krow = Ks + t * HD;
        float a = 0.f;
#pragma unroll
        for (int d = 0; d < HD; d++) a = fmaf(qreg[d], krow[d], a);
        denom += a;
        const float* vrow = Vs + t * HD + j0;
#pragma unroll
        for (int j = 0; j < 16; j++) acc[j] = fmaf(a, vrow[j], acc[j]);
    }

    const float inv = 1.f / denom;
    const size_t obase = (size_t)(s0 + i) * D_MODEL + h * HD + j0;
    __nv_bfloat162* oh = reinterpret_cast<__nv_bfloat162*>(g_at_hi + obase);
    __nv_bfloat162* ol = reinterpret_cast<__nv_bfloat162*>(g_at_lo + obase);
#pragma unroll
    for (int j = 0; j < 16; j += 2) {
        float v0 = acc[j] * inv, v1 = acc[j + 1] * inv;
        __nv_bfloat16 h0 = __float2bfloat16(v0), h1 = __float2bfloat16(v1);
        __nv_bfloat16 l0 = __float2bfloat16(v0 - __bfloat162float(h0));
        __nv_bfloat16 l1 = __float2bfloat16(v1 - __bfloat162float(h1));
        oh[j >> 1] = __nv_bfloat162(h0, h1);
        ol[j >> 1] = __nv_bfloat162(l0, l1);
    }
}

// ---------------- launch ----------------
static const int kOutSmemBytes = (CHUNK * 65 + CHUNK * HD * 2 + HD * HD + HD) * (int)sizeof(float); // ~66KB

extern "C" void kernel_launch(void* const* d_in, const int* in_sizes, int n_in,
                              void* d_out, int out_size)
{
    (void)in_sizes; (void)n_in; (void)out_size;
    const float* x    = (const float*)d_in[0];
    const float* Wqkv = (const float*)d_in[2];
    const float* Wout = (const float*)d_in[3];
    float* out = (float*)d_out;

    float* qkv_ptr;
    __nv_bfloat16 *xh, *xl, *wqh, *wql, *woh, *wol, *ath, *atl;
    cudaGetSymbolAddress((void**)&qkv_ptr, g_qkv);
    cudaGetSymbolAddress((void**)&xh, g_x_hi);
    cudaGetSymbolAddress((void**)&xl, g_x_lo);
    cudaGetSymbolAddress((void**)&wqh, g_wq_hi);
    cudaGetSymbolAddress((void**)&wql, g_wq_lo);
    cudaGetSymbolAddress((void**)&woh, g_wo_hi);
    cudaGetSymbolAddress((void**)&wol, g_wo_lo);
    cudaGetSymbolAddress((void**)&ath, g_at_hi);
    cudaGetSymbolAddress((void**)&atl, g_at_lo);

    cudaFuncSetAttribute(chunk_out_kernel,
                         cudaFuncAttributeMaxDynamicSharedMemorySize, kOutSmemBytes);
    cudaFuncSetAttribute(gemm3_mma_kernel,
                         cudaFuncAttributeMaxDynamicSharedMemorySize, GEMM_SMEM);

    // conversions
    conv_hilo_kernel<<<(S_LEN * D_MODEL / 4 + 255) / 256, 256>>>(x, xh, xl, S_LEN * D_MODEL / 4);
    {
        dim3 b(32, 8);
        dim3 gq(TRIPLE / 32, D_MODEL / 32);
        transpose_hilo_kernel<<<gq, b>>>(Wqkv, wqh, wql, D_MODEL, TRIPLE);
        dim3 go(D_MODEL / 32, D_MODEL / 32);
        transpose_hilo_kernel<<<go, b>>>(Wout, woh, wol, D_MODEL, D_MODEL);
    }

    // K1: qkv = x @ W_qkv (HMMA), phi on first 2048 cols
    {
        dim3 g(TRIPLE / 128, S_LEN / 128);
        gemm3_mma_kernel<<<g, 256, GEMM_SMEM>>>(xh, xl, wqh, wql, qkv_ptr, TRIPLE, 2 * D_MODEL);
    }

    // K2/K3/K4
    dim3 g2(NCHUNK, H_NUM);
    chunk_state_kernel<<<g2, 256>>>();
    prefix_kernel<<<H_NUM, 256>>>();
    chunk_out_kernel<<<g2, 256, kOutSmemBytes>>>();

    // K5: out = attn @ W_out (HMMA)
    {
        dim3 g(D_MODEL / 128, S_LEN / 128);
        gemm3_mma_kernel<<<g, 256, GEMM_SMEM>>>(ath, atl, woh, wol, out, D_MODEL, 0);
    }
}